// round 14
// baseline (speedup 1.0000x reference)
#include <cuda_runtime.h>
#include <float.h>

#define NB 16
#define NC 80
#define NH 256
#define NW 256
#define HW (NH*NW)
#define CHW (NC*HW)
#define TOPK 100
#define THREADS 256
#define CUT 0.99995f
#define CAP 16384
#define SORT_N 512
#define BLKS_PER_BATCH (NC*4)

// ---------------- static scratch (zero-initialized at module load) ----------------
__device__ int                g_count[NB];
__device__ int                g_overflow[NB];
__device__ int                g_done[NB];
__device__ unsigned long long g_cand[NB][CAP];

__device__ __forceinline__ unsigned fkey(float v) {
    unsigned u = __float_as_uint(v);
    return (u & 0x80000000u) ? ~u : (u | 0x80000000u);
}
__device__ __forceinline__ float fkey_inv(unsigned k) {
    unsigned u = (k & 0x80000000u) ? (k & 0x7fffffffu) : ~k;
    return __uint_as_float(u);
}
__device__ __forceinline__ unsigned long long packKey(float v, int idx) {
    return ((unsigned long long)fkey(v) << 32) | (unsigned)(~idx);
}
__device__ __forceinline__ float max4(float4 v) {
    return fmaxf(fmaxf(v.x, v.y), fmaxf(v.z, v.w));
}

// ---------------- fused: streaming scan + last-block per-batch selection ----------
__global__ void __launch_bounds__(THREADS) k_fused(const float* __restrict__ hm,
                                                   const float* __restrict__ offset,
                                                   const float* __restrict__ wh,
                                                   float* __restrict__ out) {
    const int bc = blockIdx.x >> 2;          // (b,c) plane
    const int rt = blockIdx.x & 3;           // 64-row tile
    const int b  = bc / NC;
    const int c  = bc % NC;
    const int t  = threadIdx.x;
    const int sx = t & 63;                   // 4-col strip
    const int ry = t >> 6;                   // row group 0..3
    const float* plane = hm + (size_t)bc * HW;
    const float4* p4 = (const float4*)plane;
    const int row0 = rt * 64 + ry * 16;
    const float4* base = p4 + row0 * 64 + sx;

    // ---- Phase 1: 16 streaming LDG.128, 4 running maxes (values in [0,1)) ----
    float m0 = 0.f, m1 = 0.f, m2 = 0.f, m3 = 0.f;
    #pragma unroll
    for (int r = 0; r < 16; r += 4) {
        float4 a = __ldcs(base + (r + 0) * 64);
        float4 bb = __ldcs(base + (r + 1) * 64);
        float4 cc = __ldcs(base + (r + 2) * 64);
        float4 dd = __ldcs(base + (r + 3) * 64);
        m0 = fmaxf(m0, max4(a));
        m1 = fmaxf(m1, max4(bb));
        m2 = fmaxf(m2, max4(cc));
        m3 = fmaxf(m3, max4(dd));
    }

    // ---- Phase 2 (rare): reload rows from cache, peak-test ----
    if (fmaxf(fmaxf(m0, m1), fmaxf(m2, m3)) >= CUT) {
        #pragma unroll 1
        for (int r = 0; r < 16; r++) {
            const int row = row0 + r;
            float4 v = base[r * 64];
            if (max4(v) < CUT) continue;
            float vals[4] = {v.x, v.y, v.z, v.w};
            #pragma unroll 1
            for (int e = 0; e < 4; e++) {
                float vv = vals[e];
                if (vv < CUT) continue;
                int col = sx * 4 + e;
                float mx = -FLT_MAX;
                for (int dh = -1; dh <= 1; dh++) {
                    int rr = row + dh;
                    if ((unsigned)rr >= NH) continue;
                    for (int dw = -1; dw <= 1; dw++) {
                        int wc = col + dw;
                        if ((unsigned)wc >= NW) continue;
                        mx = fmaxf(mx, plane[rr * NW + wc]);
                    }
                }
                if (vv == mx) {              // 3x3 peak (window includes self)
                    int pos = atomicAdd(&g_count[b], 1);
                    if (pos < CAP) g_cand[b][pos] = packKey(vv, c * HW + row * NW + col);
                    else g_overflow[b] = 1;
                }
            }
        }
    }

    // ---- last-block handoff (no spinning: last to increment proceeds) ----
    __shared__ int s_last;
    __threadfence();
    __syncthreads();
    if (t == 0) s_last = (atomicAdd(&g_done[b], 1) == BLKS_PER_BATCH - 1) ? 1 : 0;
    __syncthreads();
    if (!s_last) return;

    // =================== per-batch selection tail ===================
    __shared__ unsigned long long keys[SORT_N];
    __shared__ unsigned long long rk[THREADS];

    const int n = min(g_count[b], CAP);
    const bool tierC = (g_overflow[b] != 0) || (n < TOPK);
    const unsigned long long* cand = g_cand[b];

    float myscore = 0.f;
    int   myidx = 0x7fffffff;
    float myscore2 = 0.f;                    // slot t+THREADS (unused: TOPK<256)
    (void)myscore2;

    if (!tierC && n <= SORT_N) {
        // ---- Tier A: bitonic sort 512 slots with 256 threads (2 slots/thread) ----
        #pragma unroll
        for (int e = 0; e < SORT_N / THREADS; e++) {
            int i = t + THREADS * e;
            keys[i] = (i < n) ? cand[i] : 0ull;
        }
        __syncthreads();
        for (int k = 2; k <= SORT_N; k <<= 1) {
            for (int j = k >> 1; j > 0; j >>= 1) {
                #pragma unroll
                for (int e = 0; e < SORT_N / THREADS; e++) {
                    int i = t + THREADS * e;
                    int l = i ^ j;
                    if (l > i) {
                        bool desc = ((i & k) == 0);
                        unsigned long long a = keys[i], bb = keys[l];
                        if (desc ? (a < bb) : (a > bb)) { keys[i] = bb; keys[l] = a; }
                    }
                }
                __syncthreads();
            }
        }
        if (t < TOPK) {
            unsigned long long kk = keys[t];
            if (kk) { myscore = fkey_inv((unsigned)(kk >> 32)); myidx = (int)(~(unsigned)kk); }
        }
    } else if (!tierC) {
        // ---- Tier B (never taken): exact iterative selection over candidates ----
        unsigned long long prev = 0xFFFFFFFFFFFFFFFFull;
        for (int r = 0; r < TOPK; r++) {
            unsigned long long bk = 0ull;
            for (int i = t; i < n; i += THREADS) {
                unsigned long long kk = cand[i];
                if (kk < prev && kk > bk) bk = kk;
            }
            rk[t] = bk;
            __syncthreads();
            for (int off = THREADS / 2; off > 0; off >>= 1) {
                if (t < off) rk[t] = max(rk[t], rk[t + off]);
                __syncthreads();
            }
            unsigned long long top = rk[0];
            if (t == r && top) { myscore = fkey_inv((unsigned)(top >> 32)); myidx = (int)(~(unsigned)top); }
            prev = top;
            __syncthreads();
        }
    } else {
        // ---- Tier C (never taken): exact iterative over full heatmap ----
        const float* hmb = hm + (size_t)b * CHW;
        unsigned long long prev = 0xFFFFFFFFFFFFFFFFull;
        for (int r = 0; r < TOPK; r++) {
            unsigned long long bk = 0ull;
            for (int cell = t; cell < CHW; cell += THREADS) {
                float v = hmb[cell];
                unsigned long long kk = packKey(v, cell);
                if (kk >= prev || kk <= bk) continue;
                int sp = cell % HW;
                int row = sp / NW, col = sp % NW;
                const float* pl = hmb + (cell / HW) * HW;
                float mx = -FLT_MAX;
                for (int dh = -1; dh <= 1; dh++) {
                    int rr = row + dh;
                    if ((unsigned)rr >= NH) continue;
                    for (int dw = -1; dw <= 1; dw++) {
                        int wc = col + dw;
                        if ((unsigned)wc >= NW) continue;
                        mx = fmaxf(mx, pl[rr * NW + wc]);
                    }
                }
                if (v == mx) bk = kk;
            }
            rk[t] = bk;
            __syncthreads();
            for (int off = THREADS / 2; off > 0; off >>= 1) {
                if (t < off) rk[t] = max(rk[t], rk[t + off]);
                __syncthreads();
            }
            unsigned long long top = rk[0];
            if (t == r && top) { myscore = fkey_inv((unsigned)(top >> 32)); myidx = (int)(~(unsigned)top); }
            prev = top;
            __syncthreads();
        }
    }

    // ---- gather + output (layout validated: rel_err 0) ----
    if (t < TOPK) {
        float score = myscore;
        int idx = myidx;
        if (idx == 0x7fffffff) { idx = 0; score = 0.f; }
        int cls = idx / HW;
        int sp  = idx % HW;
        int y = sp / NW, x = sp % NW;
        const float* offp = offset + (size_t)b * 2 * HW;
        const float* whp  = wh     + (size_t)b * 2 * HW;
        float ox = offp[sp];
        float oy = offp[HW + sp];
        float bw = whp[sp];
        float bh = whp[HW + sp];
        float cx = (float)x + ox;
        float cy = (float)y + oy;
        float hw2 = bw * 0.5f, hh2 = bh * 0.5f;
        bool mask = score > 0.01f;

        float* ids_o = out;
        float* sc_o  = out + NB * TOPK;
        float* bb_o  = out + 2 * NB * TOPK;
        int o = b * TOPK + t;
        ids_o[o] = mask ? (float)cls : -1.f;
        sc_o[o]  = mask ? score : -1.f;
        float x1 = mask ? (cx - hw2) : -1.f;
        float y1 = mask ? (cy - hh2) : -1.f;
        float x2 = mask ? (cx + hw2) : -1.f;
        float y2 = mask ? (cy + hh2) : -1.f;
        bb_o[o * 4 + 0] = x1 * 4.0f;
        bb_o[o * 4 + 1] = y1 * 4.0f;
        bb_o[o * 4 + 2] = x2 * 4.0f;
        bb_o[o * 4 + 3] = y2 * 4.0f;
    }

    // ---- reset scratch for the next graph replay ----
    if (t == 0) { g_count[b] = 0; g_overflow[b] = 0; g_done[b] = 0; }
}

extern "C" void kernel_launch(void* const* d_in, const int* in_sizes, int n_in,
                              void* d_out, int out_size) {
    const float* hm     = (const float*)d_in[0];   // (16,80,256,256)
    const float* offset = (const float*)d_in[1];   // (16,2,256,256)
    const float* wh     = (const float*)d_in[2];   // (16,2,256,256)
    float* out = (float*)d_out;

    k_fused<<<NB * NC * 4, THREADS>>>(hm, offset, wh, out);
}

// round 15
// speedup vs baseline: 1.0599x; 1.0599x over previous
#include <cuda_runtime.h>
#include <float.h>

#define NB 16
#define NC 80
#define NH 256
#define NW 256
#define HW (NH*NW)
#define CHW (NC*HW)
#define TOPK 100
#define THREADS 256
#define CUT 0.99995f
#define CAP 16384
#define SORT_N 512
#define BLKS_PER_BATCH (NC*4)

// ---------------- static scratch (zero-initialized at module load) ----------------
__device__ int                g_count[NB];
__device__ int                g_overflow[NB];
__device__ int                g_done[NB];
__device__ unsigned long long g_cand[NB][CAP];

__device__ __forceinline__ unsigned fkey(float v) {
    unsigned u = __float_as_uint(v);
    return (u & 0x80000000u) ? ~u : (u | 0x80000000u);
}
__device__ __forceinline__ float fkey_inv(unsigned k) {
    unsigned u = (k & 0x80000000u) ? (k & 0x7fffffffu) : ~k;
    return __uint_as_float(u);
}
__device__ __forceinline__ unsigned long long packKey(float v, int idx) {
    return ((unsigned long long)fkey(v) << 32) | (unsigned)(~idx);
}
__device__ __forceinline__ float max4(float4 v) {
    return fmaxf(fmaxf(v.x, v.y), fmaxf(v.z, v.w));
}

// ---------------- fused: streaming scan + last-block per-batch selection ----------
__global__ void __launch_bounds__(THREADS) k_fused(const float* __restrict__ hm,
                                                   const float* __restrict__ offset,
                                                   const float* __restrict__ wh,
                                                   float* __restrict__ out) {
    const int bc = blockIdx.x >> 2;          // (b,c) plane
    const int rt = blockIdx.x & 3;           // 64-row tile
    const int b  = bc / NC;
    const int c  = bc % NC;
    const int t  = threadIdx.x;
    const int sx = t & 63;                   // 4-col strip
    const int ry = t >> 6;                   // row group 0..3
    const float* plane = hm + (size_t)bc * HW;
    const float4* p4 = (const float4*)plane;
    const int row0 = rt * 64 + ry * 16;
    const float4* base = p4 + row0 * 64 + sx;

    // ---- Phase 1: 16 streaming LDG.128, 4 running maxes (values in [0,1)) ----
    float m0 = 0.f, m1 = 0.f, m2 = 0.f, m3 = 0.f;
    #pragma unroll
    for (int r = 0; r < 16; r += 4) {
        float4 a = __ldcs(base + (r + 0) * 64);
        float4 bb = __ldcs(base + (r + 1) * 64);
        float4 cc = __ldcs(base + (r + 2) * 64);
        float4 dd = __ldcs(base + (r + 3) * 64);
        m0 = fmaxf(m0, max4(a));
        m1 = fmaxf(m1, max4(bb));
        m2 = fmaxf(m2, max4(cc));
        m3 = fmaxf(m3, max4(dd));
    }

    // ---- Phase 2 (rare, ~0.3% of threads): peak-test; fence ONLY here ----
    if (fmaxf(fmaxf(m0, m1), fmaxf(m2, m3)) >= CUT) {
        bool wrote = false;
        #pragma unroll 1
        for (int r = 0; r < 16; r++) {
            const int row = row0 + r;
            float4 v = base[r * 64];
            if (max4(v) < CUT) continue;
            float vals[4] = {v.x, v.y, v.z, v.w};
            #pragma unroll 1
            for (int e = 0; e < 4; e++) {
                float vv = vals[e];
                if (vv < CUT) continue;
                int col = sx * 4 + e;
                float mx = -FLT_MAX;
                for (int dh = -1; dh <= 1; dh++) {
                    int rr = row + dh;
                    if ((unsigned)rr >= NH) continue;
                    for (int dw = -1; dw <= 1; dw++) {
                        int wc = col + dw;
                        if ((unsigned)wc >= NW) continue;
                        mx = fmaxf(mx, plane[rr * NW + wc]);
                    }
                }
                if (vv == mx) {              // 3x3 peak (window includes self)
                    int pos = atomicAdd(&g_count[b], 1);
                    if (pos < CAP) g_cand[b][pos] = packKey(vv, c * HW + row * NW + col);
                    else g_overflow[b] = 1;
                    wrote = true;
                }
            }
        }
        if (wrote) __threadfence();          // order my stores before the done-increment
    }

    // ---- last-block handoff: writers' fences happen-before the increment via BAR ----
    __shared__ int s_last;
    __syncthreads();
    if (t == 0) s_last = (atomicAdd(&g_done[b], 1) == BLKS_PER_BATCH - 1) ? 1 : 0;
    __syncthreads();
    if (!s_last) return;

    // =================== per-batch selection tail ===================
    __shared__ unsigned long long keys[SORT_N];
    __shared__ unsigned long long rk[THREADS];

    const int n = min(g_count[b], CAP);
    const bool tierC = (g_overflow[b] != 0) || (n < TOPK);
    const unsigned long long* cand = g_cand[b];

    float myscore = 0.f;
    int   myidx = 0x7fffffff;

    if (!tierC && n <= SORT_N) {
        // ---- Tier A: bitonic sort 512 slots with 256 threads (2 slots/thread) ----
        #pragma unroll
        for (int e = 0; e < SORT_N / THREADS; e++) {
            int i = t + THREADS * e;
            keys[i] = (i < n) ? cand[i] : 0ull;
        }
        __syncthreads();
        for (int k = 2; k <= SORT_N; k <<= 1) {
            for (int j = k >> 1; j > 0; j >>= 1) {
                #pragma unroll
                for (int e = 0; e < SORT_N / THREADS; e++) {
                    int i = t + THREADS * e;
                    int l = i ^ j;
                    if (l > i) {
                        bool desc = ((i & k) == 0);
                        unsigned long long a = keys[i], bb = keys[l];
                        if (desc ? (a < bb) : (a > bb)) { keys[i] = bb; keys[l] = a; }
                    }
                }
                __syncthreads();
            }
        }
        if (t < TOPK) {
            unsigned long long kk = keys[t];
            if (kk) { myscore = fkey_inv((unsigned)(kk >> 32)); myidx = (int)(~(unsigned)kk); }
        }
    } else if (!tierC) {
        // ---- Tier B (never taken): exact iterative selection over candidates ----
        unsigned long long prev = 0xFFFFFFFFFFFFFFFFull;
        for (int r = 0; r < TOPK; r++) {
            unsigned long long bk = 0ull;
            for (int i = t; i < n; i += THREADS) {
                unsigned long long kk = cand[i];
                if (kk < prev && kk > bk) bk = kk;
            }
            rk[t] = bk;
            __syncthreads();
            for (int off = THREADS / 2; off > 0; off >>= 1) {
                if (t < off) rk[t] = max(rk[t], rk[t + off]);
                __syncthreads();
            }
            unsigned long long top = rk[0];
            if (t == r && top) { myscore = fkey_inv((unsigned)(top >> 32)); myidx = (int)(~(unsigned)top); }
            prev = top;
            __syncthreads();
        }
    } else {
        // ---- Tier C (never taken): exact iterative over full heatmap ----
        const float* hmb = hm + (size_t)b * CHW;
        unsigned long long prev = 0xFFFFFFFFFFFFFFFFull;
        for (int r = 0; r < TOPK; r++) {
            unsigned long long bk = 0ull;
            for (int cell = t; cell < CHW; cell += THREADS) {
                float v = hmb[cell];
                unsigned long long kk = packKey(v, cell);
                if (kk >= prev || kk <= bk) continue;
                int sp = cell % HW;
                int row = sp / NW, col = sp % NW;
                const float* pl = hmb + (cell / HW) * HW;
                float mx = -FLT_MAX;
                for (int dh = -1; dh <= 1; dh++) {
                    int rr = row + dh;
                    if ((unsigned)rr >= NH) continue;
                    for (int dw = -1; dw <= 1; dw++) {
                        int wc = col + dw;
                        if ((unsigned)wc >= NW) continue;
                        mx = fmaxf(mx, pl[rr * NW + wc]);
                    }
                }
                if (v == mx) bk = kk;
            }
            rk[t] = bk;
            __syncthreads();
            for (int off = THREADS / 2; off > 0; off >>= 1) {
                if (t < off) rk[t] = max(rk[t], rk[t + off]);
                __syncthreads();
            }
            unsigned long long top = rk[0];
            if (t == r && top) { myscore = fkey_inv((unsigned)(top >> 32)); myidx = (int)(~(unsigned)top); }
            prev = top;
            __syncthreads();
        }
    }

    // ---- gather + output (layout validated: rel_err 0) ----
    if (t < TOPK) {
        float score = myscore;
        int idx = myidx;
        if (idx == 0x7fffffff) { idx = 0; score = 0.f; }
        int cls = idx / HW;
        int sp  = idx % HW;
        int y = sp / NW, x = sp % NW;
        const float* offp = offset + (size_t)b * 2 * HW;
        const float* whp  = wh     + (size_t)b * 2 * HW;
        float ox = offp[sp];
        float oy = offp[HW + sp];
        float bw = whp[sp];
        float bh = whp[HW + sp];
        float cx = (float)x + ox;
        float cy = (float)y + oy;
        float hw2 = bw * 0.5f, hh2 = bh * 0.5f;
        bool mask = score > 0.01f;

        float* ids_o = out;
        float* sc_o  = out + NB * TOPK;
        float* bb_o  = out + 2 * NB * TOPK;
        int o = b * TOPK + t;
        ids_o[o] = mask ? (float)cls : -1.f;
        sc_o[o]  = mask ? score : -1.f;
        float x1 = mask ? (cx - hw2) : -1.f;
        float y1 = mask ? (cy - hh2) : -1.f;
        float x2 = mask ? (cx + hw2) : -1.f;
        float y2 = mask ? (cy + hh2) : -1.f;
        bb_o[o * 4 + 0] = x1 * 4.0f;
        bb_o[o * 4 + 1] = y1 * 4.0f;
        bb_o[o * 4 + 2] = x2 * 4.0f;
        bb_o[o * 4 + 3] = y2 * 4.0f;
    }

    // ---- reset scratch for the next graph replay ----
    if (t == 0) { g_count[b] = 0; g_overflow[b] = 0; g_done[b] = 0; }
}

extern "C" void kernel_launch(void* const* d_in, const int* in_sizes, int n_in,
                              void* d_out, int out_size) {
    const float* hm     = (const float*)d_in[0];   // (16,80,256,256)
    const float* offset = (const float*)d_in[1];   // (16,2,256,256)
    const float* wh     = (const float*)d_in[2];   // (16,2,256,256)
    float* out = (float*)d_out;

    k_fused<<<NB * NC * 4, THREADS>>>(hm, offset, wh, out);
}